// round 17
// baseline (speedup 1.0000x reference)
#include <cuda_runtime.h>
#include <cuda_bf16.h>
#include <cstdint>

// Problem constants (fixed by the dataset)
#define T_TOK   16384
#define N_EXP   16
#define DIM     2048
#define CAP     2048
#define SLOTS   (N_EXP * CAP)           // 32768
#define OUT_MAIN ((size_t)SLOTS * DIM)  // 67,108,864 floats
#define ROW4    (DIM / 4)               // 512 float4 per row

#define CHUNKS  64
#define CHTOK   256                     // tokens per index chunk (== idx blockDim)
#define FILLB   128                     // fill helper blocks in scatter grid

// Device scratch (no allocs allowed)
__device__ int      g_cnt [N_EXP * CHUNKS];  // per-expert per-chunk counts
__device__ int      g_off [N_EXP * CHUNKS];  // exclusive chunk offsets (the new table)
__device__ int      g_load[N_EXP];           // capacity-clipped loads
__device__ int      g_meta[T_TOK];           // per-token packed: 2 x 16b (rank<<4)|e, 0xFFFF=none
__device__ unsigned g_done;                  // idx arrival counter (scanner election)

// ---------------------------------------------------------------------------
// Kernel 1: counts + chunk-local ranks; the dynamically-LAST block (elected
// by atomicAdd return value — it is by definition already running and all
// counts are published) builds the 16x64 exclusive-offset table, g_load and
// the `loads` output tail. No barrier, no waiting block.
// ---------------------------------------------------------------------------
__global__ __launch_bounds__(CHTOK)
void idx_kernel(const int4* __restrict__ hm4,
                float* __restrict__ out, long long out_size)
{
    const int c    = blockIdx.x;
    const int tid  = threadIdx.x;
    const int lane = tid & 31;
    const int wid  = tid >> 5;            // 0..7
    const int t    = c * CHTOK + tid;
    const unsigned lt = (1u << lane) - 1u;

    int4 m[4];
    #pragma unroll
    for (int i = 0; i < 4; i++) m[i] = hm4[(size_t)t * 4 + i];
    const int* v = (const int*)m;

    unsigned bits = 0;
    #pragma unroll
    for (int e = 0; e < N_EXP; e++) bits |= (v[e] > 0 ? 1u : 0u) << e;

    __shared__ int s_cnt[8][N_EXP];
    __shared__ unsigned s_prev;

    int      k = 0;
    int      e_sel[2] = {-1, -1};
    unsigned b_sel[2] = {0, 0};
    #pragma unroll
    for (int e = 0; e < N_EXP; e++) {
        unsigned ball = __ballot_sync(0xffffffffu, (bits >> e) & 1u);
        if (lane == 0) s_cnt[wid][e] = __popc(ball);
        if (((bits >> e) & 1u) && k < 2) { e_sel[k] = e; b_sel[k] = ball; k++; }
    }
    __syncthreads();

    if (tid < N_EXP) {
        int sum = 0;
        #pragma unroll
        for (int w = 0; w < 8; w++) sum += s_cnt[w][tid];
        g_cnt[tid * CHUNKS + c] = sum;
    }

    // per-token chunk-local rank, packed into 2 x 16 bits
    unsigned meta = 0xFFFFFFFFu;
    #pragma unroll
    for (int j = 0; j < 2; j++) {
        unsigned h = 0xFFFFu;
        if (j < k) {
            const int e = e_sel[j];
            int woff = 0;
            #pragma unroll
            for (int w = 0; w < 8; w++) if (w < wid) woff += s_cnt[w][e];
            const int rank = woff + __popc(b_sel[j] & lt);   // < 256
            h = ((unsigned)rank << 4) | (unsigned)e;
        }
        meta = (meta & ~(0xFFFFu << (16 * j))) | (h << (16 * j));
    }
    g_meta[t] = (int)meta;

    // Publish, then elect the scanner: the block whose arrival is LAST.
    __threadfence();
    __syncthreads();
    if (tid == 0) s_prev = atomicAdd(&g_done, 1u);
    __syncthreads();

    if (s_prev == CHUNKS - 1) {
        // All 63 other blocks' counts are visible (they fenced before arriving).
        __threadfence();
        // 8 warps x 2 experts: shfl exclusive scan over 64 chunk counts.
        #pragma unroll
        for (int h = 0; h < 2; h++) {
            const int e = wid * 2 + h;
            int c0 = __ldcg(&g_cnt[e * CHUNKS + lane]);
            int c1 = __ldcg(&g_cnt[e * CHUNKS + 32 + lane]);
            int i0 = c0, i1 = c1;
            #pragma unroll
            for (int o = 1; o < 32; o <<= 1) {
                int n0 = __shfl_up_sync(0xffffffffu, i0, o);
                int n1 = __shfl_up_sync(0xffffffffu, i1, o);
                if (lane >= o) { i0 += n0; i1 += n1; }
            }
            const int tot0 = __shfl_sync(0xffffffffu, i0, 31);
            g_off[e * CHUNKS + lane]      = i0 - c0;
            g_off[e * CHUNKS + 32 + lane] = tot0 + i1 - c1;
            if (lane == 31) {
                const int total = tot0 + i1;
                const int load  = total < CAP ? total : CAP;
                g_load[e] = load;
                if (out_size >= (long long)(OUT_MAIN + N_EXP))
                    out[OUT_MAIN + e] = (float)load;
            }
        }
        __threadfence();
        if (tid == 0) g_done = 0u;        // replay-safe reset (launches serialize)
    }

    cudaTriggerProgrammaticLaunchCompletion();
}

// ---------------------------------------------------------------------------
// Kernel 2: fused fill + token-major scatter, PDL-launched.
// Resolution is now ONE L2 load per assignment: dst = g_off[e][c] + rank.
// ---------------------------------------------------------------------------
__global__ __launch_bounds__(256, 8)
void scatter_kernel(const float4* __restrict__ in_flow,
                    const float*  __restrict__ score,
                    float4* __restrict__ out4)
{
    const int tid = threadIdx.x;

    if (blockIdx.x < FILLB) {
        const int f = blockIdx.x;
        const int e = f >> 3;
        const int y = f & 7;
        cudaGridDependencySynchronize();
        const int load = __ldcg(&g_load[e]);
        const float4 z = make_float4(0.f, 0.f, 0.f, 0.f);
        for (int r = load + y; r < CAP; r += 8) {
            float4* o = out4 + (size_t)(e * CAP + r) * ROW4;
            __stcs(o + tid, z);
            __stcs(o + tid + 256, z);
        }
        return;
    }

    const int t = blockIdx.x - FILLB;
    const int c = t >> 8;                 // CHTOK = 256

    // Issue the streaming row read first — overlaps the PDL dependency and
    // the (tiny) resolution below.
    const float4* __restrict__ r = in_flow + (size_t)t * ROW4;
    float4 a = __ldcs(r + tid);
    float4 b = __ldcs(r + tid + 256);

    cudaGridDependencySynchronize();

    __shared__ int   s_dst[2];
    __shared__ float s_g[2];
    if (tid < 2) {
        const int meta = __ldcg(&g_meta[t]);
        const unsigned h = ((unsigned)meta >> (16 * tid)) & 0xFFFFu;
        int   dst = -1;
        float g   = 0.0f;
        if (h != 0xFFFFu) {
            const int e    = (int)(h & 15u);
            const int rank = (int)(h >> 4);
            const int pos  = __ldcg(&g_off[e * CHUNKS + c]) + rank;
            if (pos < CAP) dst = e * CAP + pos;
            g = __ldg(&score[t * N_EXP + e]);
        }
        s_dst[tid] = dst;
        s_g[tid]   = g;
    }
    __syncthreads();

    const int d0 = s_dst[0];
    const int d1 = s_dst[1];
    if (d0 < 0 && d1 < 0) return;

    const float g0 = s_g[0];
    const float g1 = s_g[1];

    if (d0 >= 0) {
        float4* o = out4 + (size_t)d0 * ROW4;
        __stcs(o + tid,       make_float4(a.x * g0, a.y * g0, a.z * g0, a.w * g0));
        __stcs(o + tid + 256, make_float4(b.x * g0, b.y * g0, b.z * g0, b.w * g0));
    }
    if (d1 >= 0) {
        float4* o = out4 + (size_t)d1 * ROW4;
        __stcs(o + tid,       make_float4(a.x * g1, a.y * g1, a.z * g1, a.w * g1));
        __stcs(o + tid + 256, make_float4(b.x * g1, b.y * g1, b.z * g1, b.w * g1));
    }
}

extern "C" void kernel_launch(void* const* d_in, const int* in_sizes, int n_in,
                              void* d_out, int out_size)
{
    const float* in_flow  = (const float*)d_in[0];   // [T, D] f32
    const int*   hot_mask = (const int*)  d_in[1];   // [T, E] i32
    const float* score    = (const float*)d_in[2];   // [T, E] f32
    float*       out      = (float*)d_out;

    idx_kernel<<<CHUNKS, CHTOK>>>((const int4*)hot_mask, out,
                                  (long long)out_size);

    // PDL launch: scatter grid comes up while idx drains; device-side
    // griddepcontrol.wait enforces the dependency with HW guarantees.
    cudaLaunchConfig_t cfg = {};
    cfg.gridDim  = dim3(T_TOK + FILLB, 1, 1);
    cfg.blockDim = dim3(256, 1, 1);
    cudaLaunchAttribute attr[1];
    attr[0].id = cudaLaunchAttributeProgrammaticStreamSerialization;
    attr[0].val.programmaticStreamSerializationAllowed = 1;
    cfg.attrs    = attr;
    cfg.numAttrs = 1;
    cudaError_t err = cudaLaunchKernelEx(&cfg, scatter_kernel,
                                         (const float4*)in_flow, score,
                                         (float4*)out);
    if (err != cudaSuccess) {
        // Fallback: plain ordered launch (still correct).
        scatter_kernel<<<T_TOK + FILLB, 256>>>((const float4*)in_flow, score,
                                               (float4*)out);
    }
}